// round 6
// baseline (speedup 1.0000x reference)
#include <cuda_runtime.h>
#include <cuda_bf16.h>

// Problem constants (fixed shapes)
#define NN 100000
#define EE 1600000
#define FIN 128
#define FHID 128
#define FOUT 64

// ---------------- device scratch (static globals; no runtime alloc) -------------
// Referenced ONLY from device code by symbol name.
__device__ int   g_cnt[NN];
__device__ int   g_off[NN + 1];
__device__ int   g_cur[NN];
__device__ float g_dinv[NN];
__device__ int   g_csr[EE];
__device__ float g_h [NN * FHID];   // x @ W1
__device__ float g_a [NN * FHID];   // relu(Ahat@h + b1)
__device__ float g_t2[NN * FOUT];   // g_a @ W2

// ---------------- degree / CSR construction ------------------------------------
__global__ void k_zero_cnt() {
    int i = blockIdx.x * blockDim.x + threadIdx.x;
    if (i < NN) g_cnt[i] = 0;
}

// edge_index is INT32 (JAX x64 disabled): layout [2, E] -> src = ei[e], dst = ei[E+e]
__global__ void k_count(const int* __restrict__ ei) {
    int e = blockIdx.x * blockDim.x + threadIdx.x;
    if (e < EE) {
        int d = ei[EE + e];
        atomicAdd(&g_cnt[d], 1);
    }
}

__global__ void k_dinv() {
    int i = blockIdx.x * blockDim.x + threadIdx.x;
    if (i < NN) g_dinv[i] = rsqrtf((float)(g_cnt[i] + 1));  // +1 self-loop
}

// single-block exclusive scan of g_cnt -> g_off (and g_cur copy)
__global__ void k_scan() {
    __shared__ int warpsum[32];
    __shared__ int carry_s;
    const int tid  = threadIdx.x;
    const int lane = tid & 31;
    const int wid  = tid >> 5;
    if (tid == 0) carry_s = 0;
    __syncthreads();

    for (int base = 0; base < NN; base += 1024) {
        int i = base + tid;
        int v = (i < NN) ? g_cnt[i] : 0;
        // inclusive warp scan
        int s = v;
        #pragma unroll
        for (int d = 1; d < 32; d <<= 1) {
            int t = __shfl_up_sync(0xffffffffu, s, d);
            if (lane >= d) s += t;
        }
        if (lane == 31) warpsum[wid] = s;
        __syncthreads();
        if (wid == 0) {
            int ws = warpsum[lane];
            #pragma unroll
            for (int d = 1; d < 32; d <<= 1) {
                int t = __shfl_up_sync(0xffffffffu, ws, d);
                if (lane >= d) ws += t;
            }
            warpsum[lane] = ws;
        }
        __syncthreads();
        int block_excl = (wid == 0) ? 0 : warpsum[wid - 1];
        int incl  = s + block_excl;
        int total = warpsum[31];
        if (i < NN) {
            int excl = carry_s + incl - v;
            g_off[i] = excl;
            g_cur[i] = excl;
        }
        __syncthreads();            // everyone has read carry_s
        if (tid == 0) carry_s += total;
        __syncthreads();            // carry ready for next chunk
    }
    if (tid == 0) g_off[NN] = carry_s;
}

__global__ void k_fill(const int* __restrict__ ei) {
    int e = blockIdx.x * blockDim.x + threadIdx.x;
    if (e < EE) {
        int d = ei[EE + e];
        int s = ei[e];
        int p = atomicAdd(&g_cur[d], 1);
        g_csr[p] = s;
    }
}

// ---------------- dense GEMM: C[NN x OUTC] = X[NN x 128] @ W[128 x OUTC] ----------
// 256 threads, 64 rows per block, K chunked by 32.
// MODE 0: X = x (arg),  C = g_h   (OUTC=128)
// MODE 1: X = g_a,      C = g_t2  (OUTC=64)
template <int OUTC, int CTN, int RT, int MODE>
__global__ void gemm_k(const float* __restrict__ Xarg, const float* __restrict__ W) {
    const float* __restrict__ X = (MODE == 0) ? Xarg : (const float*)g_a;
    float* __restrict__ C       = (MODE == 0) ? g_h  : g_t2;

    __shared__ float sX[64 * 32];
    __shared__ float sW[32 * OUTC];
    const int t    = threadIdx.x;
    const int cth  = t % CTN;          // column-thread (covers OUTC via float4)
    const int rg   = t / CTN;          // row group index
    const int rowB = blockIdx.x * 64;
    const int row0 = rowB + rg * RT;

    float acc[RT][4];
    #pragma unroll
    for (int r = 0; r < RT; ++r) { acc[r][0] = acc[r][1] = acc[r][2] = acc[r][3] = 0.f; }

    for (int kb = 0; kb < 128; kb += 32) {
        // load X tile: 64 rows x 32 k  (512 float4)
        #pragma unroll
        for (int i = t; i < 512; i += 256) {
            int r  = i >> 3;
            int c4 = i & 7;
            int gr = rowB + r;
            float4 v = (gr < NN)
                ? ((const float4*)X)[gr * 32 + (kb >> 2) + c4]
                : make_float4(0.f, 0.f, 0.f, 0.f);
            ((float4*)sX)[r * 8 + c4] = v;
        }
        // load W tile: 32 x OUTC
        #pragma unroll
        for (int i = t; i < (32 * OUTC) / 4; i += 256) {
            ((float4*)sW)[i] = ((const float4*)W)[(kb * OUTC) / 4 + i];
        }
        __syncthreads();
        #pragma unroll
        for (int k = 0; k < 32; ++k) {
            float4 w = ((const float4*)sW)[k * (OUTC / 4) + cth];
            #pragma unroll
            for (int r = 0; r < RT; ++r) {
                float xv = sX[(rg * RT + r) * 32 + k];
                acc[r][0] += xv * w.x;
                acc[r][1] += xv * w.y;
                acc[r][2] += xv * w.z;
                acc[r][3] += xv * w.w;
            }
        }
        __syncthreads();
    }
    #pragma unroll
    for (int r = 0; r < RT; ++r) {
        int gr = row0 + r;
        if (gr < NN)
            ((float4*)C)[gr * (OUTC / 4) + cth] =
                make_float4(acc[r][0], acc[r][1], acc[r][2], acc[r][3]);
    }
}

// ---------------- gather SpMM (layer 1): 128 cols, one warp per node -----------
// reads g_h, writes g_a = relu(Ahat@g_h + b1)
__global__ void spmm1(const float* __restrict__ b1) {
    int gw   = (blockIdx.x * blockDim.x + threadIdx.x) >> 5;
    int lane = threadIdx.x & 31;
    if (gw >= NN) return;
    const float4* H4 = (const float4*)g_h;
    float dv = g_dinv[gw];
    float sl = dv * dv;
    float4 h0 = H4[(size_t)gw * 32 + lane];
    float4 acc = make_float4(h0.x * sl, h0.y * sl, h0.z * sl, h0.w * sl);
    int e0 = g_off[gw], e1 = g_off[gw + 1];
    for (int e = e0; e < e1; ++e) {
        int s = g_csr[e];
        float nm = dv * g_dinv[s];
        float4 v = H4[(size_t)s * 32 + lane];
        acc.x += v.x * nm;
        acc.y += v.y * nm;
        acc.z += v.z * nm;
        acc.w += v.w * nm;
    }
    float4 b = ((const float4*)b1)[lane];
    acc.x = fmaxf(acc.x + b.x, 0.f);
    acc.y = fmaxf(acc.y + b.y, 0.f);
    acc.z = fmaxf(acc.z + b.z, 0.f);
    acc.w = fmaxf(acc.w + b.w, 0.f);
    ((float4*)g_a)[(size_t)gw * 32 + lane] = acc;
}

// ---------------- gather SpMM (layer 2): 64 cols, one warp per node ------------
// reads g_t2, writes out = Ahat@g_t2 + b2
__global__ void spmm2(const float* __restrict__ b2, float* __restrict__ O) {
    int gw   = (blockIdx.x * blockDim.x + threadIdx.x) >> 5;
    int lane = threadIdx.x & 31;
    if (gw >= NN) return;
    const float2* T2 = (const float2*)g_t2;
    float dv = g_dinv[gw];
    float sl = dv * dv;
    float2 t0 = T2[(size_t)gw * 32 + lane];
    float2 acc = make_float2(t0.x * sl, t0.y * sl);
    int e0 = g_off[gw], e1 = g_off[gw + 1];
    for (int e = e0; e < e1; ++e) {
        int s = g_csr[e];
        float nm = dv * g_dinv[s];
        float2 v = T2[(size_t)s * 32 + lane];
        acc.x += v.x * nm;
        acc.y += v.y * nm;
    }
    float2 b = ((const float2*)b2)[lane];
    ((float2*)O)[(size_t)gw * 32 + lane] = make_float2(acc.x + b.x, acc.y + b.y);
}

// ---------------- launch ---------------------------------------------------------
extern "C" void kernel_launch(void* const* d_in, const int* in_sizes, int n_in,
                              void* d_out, int out_size) {
    const float* x  = (const float*)d_in[0];
    const int*   ei = (const int*)d_in[1];     // int32 [2, E]
    const float* W1 = (const float*)d_in[2];
    const float* b1 = (const float*)d_in[3];
    const float* W2 = (const float*)d_in[4];
    const float* b2 = (const float*)d_in[5];
    float*       out = (float*)d_out;

    const int TB = 256;
    k_zero_cnt<<<(NN + TB - 1) / TB, TB>>>();
    k_count  <<<(EE + TB - 1) / TB, TB>>>(ei);
    k_dinv   <<<(NN + TB - 1) / TB, TB>>>();
    k_scan   <<<1, 1024>>>();
    k_fill   <<<(EE + TB - 1) / TB, TB>>>(ei);

    // layer 1: g_h = x @ W1 ; g_a = relu(Ahat @ g_h + b1)
    gemm_k<128, 32, 8, 0><<<(NN + 63) / 64, 256>>>(x, W1);
    spmm1<<<(NN * 32 + TB - 1) / TB, TB>>>(b1);

    // layer 2: g_t2 = g_a @ W2 ; out = Ahat @ g_t2 + b2
    gemm_k<64, 16, 4, 1><<<(NN + 63) / 64, 256>>>(x /*unused*/, W2);
    spmm2<<<(NN * 32 + TB - 1) / TB, TB>>>(b2, out);
}

// round 7
// speedup vs baseline: 1.1995x; 1.1995x over previous
#include <cuda_runtime.h>
#include <cuda_bf16.h>

// Problem constants (fixed shapes)
#define NN 100000
#define EE 1600000
#define FIN 128
#define FHID 128
#define FOUT 64
#define SCAN_CHUNK 1024
#define SCAN_BLOCKS ((NN + SCAN_CHUNK - 1) / SCAN_CHUNK)   // 98

// ---------------- device scratch (static globals; no runtime alloc) -------------
__device__ int   g_cnt[NN];
__device__ int   g_off[NN + 1];
__device__ int   g_cur[NN];
__device__ int   g_part[SCAN_BLOCKS];
__device__ int   g_pbase[SCAN_BLOCKS];
__device__ float g_dinv[NN];
__device__ int   g_csr[EE];
__device__ float g_h [NN * FHID];   // x @ W1
__device__ float g_a [NN * FHID];   // relu(Ahat@h + b1)
__device__ float g_t2[NN * FOUT];   // g_a @ W2

// ---------------- degree / CSR construction ------------------------------------
__global__ void k_zero_cnt() {
    int i = blockIdx.x * blockDim.x + threadIdx.x;
    if (i < NN) g_cnt[i] = 0;
}

// edge_index is INT32: layout [2, E] -> src = ei[e], dst = ei[E+e]
__global__ void k_count(const int* __restrict__ ei) {
    int e = blockIdx.x * blockDim.x + threadIdx.x;
    if (e < EE) {
        int d = ei[EE + e];
        atomicAdd(&g_cnt[d], 1);
    }
}

__global__ void k_dinv() {
    int i = blockIdx.x * blockDim.x + threadIdx.x;
    if (i < NN) g_dinv[i] = rsqrtf((float)(g_cnt[i] + 1));  // +1 self-loop
}

// ---- phase 1: per-block exclusive scan into g_off; block total into g_part ----
__global__ void k_scan_part() {
    __shared__ int warpsum[32];
    const int tid  = threadIdx.x;
    const int lane = tid & 31;
    const int wid  = tid >> 5;
    const int i = blockIdx.x * SCAN_CHUNK + tid;

    int v = (i < NN) ? g_cnt[i] : 0;
    int s = v;
    #pragma unroll
    for (int d = 1; d < 32; d <<= 1) {
        int t = __shfl_up_sync(0xffffffffu, s, d);
        if (lane >= d) s += t;
    }
    if (lane == 31) warpsum[wid] = s;
    __syncthreads();
    if (wid == 0) {
        int ws = warpsum[lane];
        #pragma unroll
        for (int d = 1; d < 32; d <<= 1) {
            int t = __shfl_up_sync(0xffffffffu, ws, d);
            if (lane >= d) ws += t;
        }
        warpsum[lane] = ws;
    }
    __syncthreads();
    int block_excl = (wid == 0) ? 0 : warpsum[wid - 1];
    int excl = s + block_excl - v;           // exclusive within this block
    if (i < NN) g_off[i] = excl;
    if (tid == SCAN_CHUNK - 1 || i == NN - 1) {
        // last live thread of the block records the block total
        if (tid == SCAN_CHUNK - 1) g_part[blockIdx.x] = s + block_excl;
        else if (i == NN - 1)      g_part[blockIdx.x] = s + block_excl;
    }
}

// ---- phase 2: scan the 98 block totals (tiny, one block) ----------------------
__global__ void k_scan_base() {
    __shared__ int sp[SCAN_BLOCKS];
    int tid = threadIdx.x;
    if (tid < SCAN_BLOCKS) sp[tid] = g_part[tid];
    __syncthreads();
    if (tid == 0) {
        int run = 0;
        for (int b = 0; b < SCAN_BLOCKS; ++b) {
            int t = sp[b];
            sp[b] = run;
            run += t;
        }
        g_off[NN] = run;
    }
    __syncthreads();
    if (tid < SCAN_BLOCKS) g_pbase[tid] = sp[tid];
}

// ---- phase 3: add block base; mirror into g_cur --------------------------------
__global__ void k_scan_add() {
    int i = blockIdx.x * SCAN_CHUNK + threadIdx.x;
    if (i < NN) {
        int o = g_off[i] + g_pbase[blockIdx.x];
        g_off[i] = o;
        g_cur[i] = o;
    }
}

__global__ void k_fill(const int* __restrict__ ei) {
    int e = blockIdx.x * blockDim.x + threadIdx.x;
    if (e < EE) {
        int d = ei[EE + e];
        int s = ei[e];
        int p = atomicAdd(&g_cur[d], 1);
        g_csr[p] = s;
    }
}

// ---------------- dense GEMM: C[NN x OUTC] = X[NN x 128] @ W[128 x OUTC] ----------
// 256 threads, 64 rows per block, K chunked by 32.
// MODE 0: X = x (arg),  C = g_h   (OUTC=128)
// MODE 1: X = g_a,      C = g_t2  (OUTC=64)
template <int OUTC, int CTN, int RT, int MODE>
__global__ void gemm_k(const float* __restrict__ Xarg, const float* __restrict__ W) {
    const float* __restrict__ X = (MODE == 0) ? Xarg : (const float*)g_a;
    float* __restrict__ C       = (MODE == 0) ? g_h  : g_t2;

    __shared__ float sX[64 * 32];
    __shared__ float sW[32 * OUTC];
    const int t    = threadIdx.x;
    const int cth  = t % CTN;
    const int rg   = t / CTN;
    const int rowB = blockIdx.x * 64;
    const int row0 = rowB + rg * RT;

    float acc[RT][4];
    #pragma unroll
    for (int r = 0; r < RT; ++r) { acc[r][0] = acc[r][1] = acc[r][2] = acc[r][3] = 0.f; }

    for (int kb = 0; kb < 128; kb += 32) {
        #pragma unroll
        for (int i = t; i < 512; i += 256) {
            int r  = i >> 3;
            int c4 = i & 7;
            int gr = rowB + r;
            float4 v = (gr < NN)
                ? ((const float4*)X)[gr * 32 + (kb >> 2) + c4]
                : make_float4(0.f, 0.f, 0.f, 0.f);
            ((float4*)sX)[r * 8 + c4] = v;
        }
        #pragma unroll
        for (int i = t; i < (32 * OUTC) / 4; i += 256) {
            ((float4*)sW)[i] = ((const float4*)W)[(kb * OUTC) / 4 + i];
        }
        __syncthreads();
        #pragma unroll
        for (int k = 0; k < 32; ++k) {
            float4 w = ((const float4*)sW)[k * (OUTC / 4) + cth];
            #pragma unroll
            for (int r = 0; r < RT; ++r) {
                float xv = sX[(rg * RT + r) * 32 + k];
                acc[r][0] += xv * w.x;
                acc[r][1] += xv * w.y;
                acc[r][2] += xv * w.z;
                acc[r][3] += xv * w.w;
            }
        }
        __syncthreads();
    }
    #pragma unroll
    for (int r = 0; r < RT; ++r) {
        int gr = row0 + r;
        if (gr < NN)
            ((float4*)C)[gr * (OUTC / 4) + cth] =
                make_float4(acc[r][0], acc[r][1], acc[r][2], acc[r][3]);
    }
}

// ---------------- gather SpMM (layer 1): 128 cols, one warp per node -----------
// reads g_h, writes g_a = relu(Ahat@g_h + b1). 2-way unrolled edge loop for MLP.
__global__ void spmm1(const float* __restrict__ b1) {
    int gw   = (blockIdx.x * blockDim.x + threadIdx.x) >> 5;
    int lane = threadIdx.x & 31;
    if (gw >= NN) return;
    const float4* H4 = (const float4*)g_h;
    float dv = g_dinv[gw];
    float sl = dv * dv;
    float4 h0 = H4[(size_t)gw * 32 + lane];
    float4 acc = make_float4(h0.x * sl, h0.y * sl, h0.z * sl, h0.w * sl);
    int e  = g_off[gw], e1 = g_off[gw + 1];
    for (; e + 2 <= e1; e += 2) {
        int s0 = g_csr[e];
        int s1 = g_csr[e + 1];
        float n0 = dv * g_dinv[s0];
        float n1 = dv * g_dinv[s1];
        float4 v0 = H4[(size_t)s0 * 32 + lane];
        float4 v1 = H4[(size_t)s1 * 32 + lane];
        acc.x += v0.x * n0 + v1.x * n1;
        acc.y += v0.y * n0 + v1.y * n1;
        acc.z += v0.z * n0 + v1.z * n1;
        acc.w += v0.w * n0 + v1.w * n1;
    }
    if (e < e1) {
        int s = g_csr[e];
        float nm = dv * g_dinv[s];
        float4 v = H4[(size_t)s * 32 + lane];
        acc.x += v.x * nm;
        acc.y += v.y * nm;
        acc.z += v.z * nm;
        acc.w += v.w * nm;
    }
    float4 b = ((const float4*)b1)[lane];
    acc.x = fmaxf(acc.x + b.x, 0.f);
    acc.y = fmaxf(acc.y + b.y, 0.f);
    acc.z = fmaxf(acc.z + b.z, 0.f);
    acc.w = fmaxf(acc.w + b.w, 0.f);
    ((float4*)g_a)[(size_t)gw * 32 + lane] = acc;
}

// ---------------- gather SpMM (layer 2): 64 cols, one warp per node ------------
// reads g_t2, writes out = Ahat@g_t2 + b2. 2-way unrolled.
__global__ void spmm2(const float* __restrict__ b2, float* __restrict__ O) {
    int gw   = (blockIdx.x * blockDim.x + threadIdx.x) >> 5;
    int lane = threadIdx.x & 31;
    if (gw >= NN) return;
    const float2* T2 = (const float2*)g_t2;
    float dv = g_dinv[gw];
    float sl = dv * dv;
    float2 t0 = T2[(size_t)gw * 32 + lane];
    float2 acc = make_float2(t0.x * sl, t0.y * sl);
    int e  = g_off[gw], e1 = g_off[gw + 1];
    for (; e + 2 <= e1; e += 2) {
        int s0 = g_csr[e];
        int s1 = g_csr[e + 1];
        float n0 = dv * g_dinv[s0];
        float n1 = dv * g_dinv[s1];
        float2 v0 = T2[(size_t)s0 * 32 + lane];
        float2 v1 = T2[(size_t)s1 * 32 + lane];
        acc.x += v0.x * n0 + v1.x * n1;
        acc.y += v0.y * n0 + v1.y * n1;
    }
    if (e < e1) {
        int s = g_csr[e];
        float nm = dv * g_dinv[s];
        float2 v = T2[(size_t)s * 32 + lane];
        acc.x += v.x * nm;
        acc.y += v.y * nm;
    }
    float2 b = ((const float2*)b2)[lane];
    ((float2*)O)[(size_t)gw * 32 + lane] = make_float2(acc.x + b.x, acc.y + b.y);
}

// ---------------- launch ---------------------------------------------------------
extern "C" void kernel_launch(void* const* d_in, const int* in_sizes, int n_in,
                              void* d_out, int out_size) {
    const float* x  = (const float*)d_in[0];
    const int*   ei = (const int*)d_in[1];     // int32 [2, E]
    const float* W1 = (const float*)d_in[2];
    const float* b1 = (const float*)d_in[3];
    const float* W2 = (const float*)d_in[4];
    const float* b2 = (const float*)d_in[5];
    float*       out = (float*)d_out;

    const int TB = 256;
    k_zero_cnt<<<(NN + TB - 1) / TB, TB>>>();
    k_count   <<<(EE + TB - 1) / TB, TB>>>(ei);
    k_dinv    <<<(NN + TB - 1) / TB, TB>>>();
    k_scan_part<<<SCAN_BLOCKS, SCAN_CHUNK>>>();
    k_scan_base<<<1, 128>>>();
    k_scan_add <<<SCAN_BLOCKS, SCAN_CHUNK>>>();
    k_fill    <<<(EE + TB - 1) / TB, TB>>>(ei);

    // layer 1: g_h = x @ W1 ; g_a = relu(Ahat @ g_h + b1)
    gemm_k<128, 32, 8, 0><<<(NN + 63) / 64, 256>>>(x, W1);
    spmm1<<<(NN * 32 + TB - 1) / TB, TB>>>(b1);

    // layer 2: g_t2 = g_a @ W2 ; out = Ahat @ g_t2 + b2
    gemm_k<64, 16, 4, 1><<<(NN + 63) / 64, 256>>>(x /*unused*/, W2);
    spmm2<<<(NN * 32 + TB - 1) / TB, TB>>>(b2, out);
}

// round 8
// speedup vs baseline: 1.2341x; 1.0288x over previous
#include <cuda_runtime.h>
#include <cuda_fp16.h>

// Problem constants (fixed shapes)
#define NN 100000
#define EE 1600000
#define SCAN_CHUNK 1024
#define SCAN_BLOCKS ((NN + SCAN_CHUNK - 1) / SCAN_CHUNK)   // 98

// ---------------- device scratch (static globals; no runtime alloc) -------------
__device__ int    g_cnt[NN];
__device__ int    g_off[NN + 1];
__device__ int    g_cur[NN];
__device__ int    g_part[SCAN_BLOCKS];
__device__ int    g_pbase[SCAN_BLOCKS];
__device__ float  g_dinv[NN];
__device__ int    g_csr[EE];
__device__ __half g_h [NN * 128];   // x @ W1          (fp16 storage, fp32 math)
__device__ __half g_a [NN * 128];   // relu(Ahat@h+b1)
__device__ __half g_t2[NN * 64];    // g_a @ W2

// ---------------- degree / CSR construction ------------------------------------
__global__ void k_zero_cnt() {
    int i = blockIdx.x * blockDim.x + threadIdx.x;
    if (i < NN) g_cnt[i] = 0;
}

// edge_index is INT32: layout [2, E] -> src = ei[e], dst = ei[E+e]
__global__ void k_count(const int* __restrict__ ei) {
    int e = blockIdx.x * blockDim.x + threadIdx.x;
    if (e < EE) atomicAdd(&g_cnt[ei[EE + e]], 1);
}

// phase 1: per-block exclusive scan into g_off; block total into g_part; also dinv
__global__ void k_scan_part() {
    __shared__ int warpsum[32];
    const int tid  = threadIdx.x;
    const int lane = tid & 31;
    const int wid  = tid >> 5;
    const int i = blockIdx.x * SCAN_CHUNK + tid;

    int v = (i < NN) ? g_cnt[i] : 0;
    if (i < NN) g_dinv[i] = rsqrtf((float)(v + 1));   // +1 self-loop
    int s = v;
    #pragma unroll
    for (int d = 1; d < 32; d <<= 1) {
        int t = __shfl_up_sync(0xffffffffu, s, d);
        if (lane >= d) s += t;
    }
    if (lane == 31) warpsum[wid] = s;
    __syncthreads();
    if (wid == 0) {
        int ws = warpsum[lane];
        #pragma unroll
        for (int d = 1; d < 32; d <<= 1) {
            int t = __shfl_up_sync(0xffffffffu, ws, d);
            if (lane >= d) ws += t;
        }
        warpsum[lane] = ws;
    }
    __syncthreads();
    int block_excl = (wid == 0) ? 0 : warpsum[wid - 1];
    if (i < NN) g_off[i] = s + block_excl - v;
    if (tid == SCAN_CHUNK - 1) g_part[blockIdx.x] = s + block_excl;
}

// phase 2: scan the 98 block totals
__global__ void k_scan_base() {
    __shared__ int sp[SCAN_BLOCKS];
    int tid = threadIdx.x;
    if (tid < SCAN_BLOCKS) sp[tid] = g_part[tid];
    __syncthreads();
    if (tid == 0) {
        int run = 0;
        for (int b = 0; b < SCAN_BLOCKS; ++b) { int t = sp[b]; sp[b] = run; run += t; }
        g_off[NN] = run;
    }
    __syncthreads();
    if (tid < SCAN_BLOCKS) g_pbase[tid] = sp[tid];
}

// phase 3: add block base; mirror into g_cur
__global__ void k_scan_add() {
    int i = blockIdx.x * SCAN_CHUNK + threadIdx.x;
    if (i < NN) {
        int o = g_off[i] + g_pbase[blockIdx.x];
        g_off[i] = o;
        g_cur[i] = o;
    }
}

__global__ void k_fill(const int* __restrict__ ei) {
    int e = blockIdx.x * blockDim.x + threadIdx.x;
    if (e < EE) {
        int d = ei[EE + e];
        int s = ei[e];
        g_csr[atomicAdd(&g_cur[d], 1)] = s;
    }
}

// ---------------- dense GEMM: C[NN x N] = X[NN x 128] @ W[128 x N], C in fp16 ----
// 128-row tile, 256 threads, 8x8 (N=128) or 8x4 (N=64) register blocking.
// MODE 0: X = x (fp32 arg), C = g_h    (N=128)
// MODE 1: X = g_a (fp16),   C = g_t2   (N=64)
template <int N, int MODE>
__global__ __launch_bounds__(256) void gemm_k(const float* __restrict__ Xf,
                                              const float* __restrict__ W) {
    __shared__ float sA[8 * 128];       // sA[k][m]
    __shared__ float sB[8 * N];         // sB[k][n]
    const int t  = threadIdx.x;
    const int tx = t & 15;              // 16 row-groups
    const int ty = t >> 4;              // 16 col-groups
    const int rowB = blockIdx.x * 128;

    constexpr int NB = (N == 128) ? 8 : 4;
    float acc[8][NB];
    #pragma unroll
    for (int i = 0; i < 8; ++i)
        #pragma unroll
        for (int j = 0; j < NB; ++j) acc[i][j] = 0.f;

    // loader indices
    const int arow = t >> 1;            // 0..127
    const int asub = t & 1;             // which half of the 8-k group
    const int bk   = (N == 128) ? (t >> 5) : (t >> 4);
    const int bc4  = (N == 128) ? (t & 31) : (t & 15);
    const bool bact = (N == 128) || (t < 128);

    const __half* __restrict__ Ah = (const __half*)g_a;
    __half* __restrict__ Ch = (MODE == 0) ? g_h : g_t2;

    float4 ra;  uint2 rah;  float4 rb;

    // prefetch chunk 0
    {
        int gr = rowB + arow;
        if (MODE == 0) {
            ra = (gr < NN) ? ((const float4*)Xf)[gr * 32 + asub]
                           : make_float4(0.f, 0.f, 0.f, 0.f);
        } else {
            rah = (gr < NN) ? *(const uint2*)(Ah + (size_t)gr * 128 + asub * 4)
                            : make_uint2(0u, 0u);
        }
        if (bact) rb = ((const float4*)W)[bk * (N / 4) + bc4];
    }

    #pragma unroll 1
    for (int kb = 0; kb < 16; ++kb) {
        // stage regs -> smem
        if (MODE == 0) {
            sA[(asub * 4 + 0) * 128 + arow] = ra.x;
            sA[(asub * 4 + 1) * 128 + arow] = ra.y;
            sA[(asub * 4 + 2) * 128 + arow] = ra.z;
            sA[(asub * 4 + 3) * 128 + arow] = ra.w;
        } else {
            float2 p0 = __half22float2(*(__half2*)&rah.x);
            float2 p1 = __half22float2(*(__half2*)&rah.y);
            sA[(asub * 4 + 0) * 128 + arow] = p0.x;
            sA[(asub * 4 + 1) * 128 + arow] = p0.y;
            sA[(asub * 4 + 2) * 128 + arow] = p1.x;
            sA[(asub * 4 + 3) * 128 + arow] = p1.y;
        }
        if (bact) ((float4*)sB)[bk * (N / 4) + bc4] = rb;
        __syncthreads();

        // prefetch next chunk
        if (kb < 15) {
            int gr = rowB + arow;
            if (MODE == 0) {
                ra = (gr < NN) ? ((const float4*)Xf)[gr * 32 + (kb + 1) * 2 + asub]
                               : make_float4(0.f, 0.f, 0.f, 0.f);
            } else {
                rah = (gr < NN) ? *(const uint2*)(Ah + (size_t)gr * 128 + (kb + 1) * 8 + asub * 4)
                                : make_uint2(0u, 0u);
            }
            if (bact) rb = ((const float4*)W)[((kb + 1) * 8 + bk) * (N / 4) + bc4];
        }

        // compute 8 k-steps
        #pragma unroll
        for (int k = 0; k < 8; ++k) {
            float4 a0 = *(const float4*)&sA[k * 128 + tx * 4];
            float4 a1 = *(const float4*)&sA[k * 128 + tx * 4 + 64];
            float av[8] = {a0.x, a0.y, a0.z, a0.w, a1.x, a1.y, a1.z, a1.w};
            float4 b0 = *(const float4*)&sB[k * N + ty * 4];
            float bv[NB];
            bv[0] = b0.x; bv[1] = b0.y; bv[2] = b0.z; bv[3] = b0.w;
            if (N == 128) {
                float4 b1 = *(const float4*)&sB[k * N + ty * 4 + 64];
                bv[4] = b1.x; bv[5] = b1.y; bv[6] = b1.z; bv[7] = b1.w;
            }
            #pragma unroll
            for (int i = 0; i < 8; ++i)
                #pragma unroll
                for (int j = 0; j < NB; ++j)
                    acc[i][j] += av[i] * bv[j];
        }
        __syncthreads();
    }

    // store C as fp16
    #pragma unroll
    for (int i = 0; i < 8; ++i) {
        int m = rowB + tx * 4 + ((i < 4) ? i : (64 + i - 4));
        if (m >= NN) continue;
        {
            uint2 u;
            *(__half2*)&u.x = __floats2half2_rn(acc[i][0], acc[i][1]);
            *(__half2*)&u.y = __floats2half2_rn(acc[i][2], acc[i][3]);
            *(uint2*)(Ch + (size_t)m * N + ty * 4) = u;
        }
        if (N == 128) {
            uint2 u;
            *(__half2*)&u.x = __floats2half2_rn(acc[i][4], acc[i][5]);
            *(__half2*)&u.y = __floats2half2_rn(acc[i][6], acc[i][7]);
            *(uint2*)(Ch + (size_t)m * N + ty * 4 + 64) = u;
        }
    }
}

// ---------------- gather SpMM (layer 1): 128 cols fp16, one warp per node ------
// reads g_h (fp16), writes g_a (fp16) = relu(Ahat@g_h + b1); fp32 accumulation
__global__ void spmm1(const float* __restrict__ b1) {
    int gw   = (blockIdx.x * blockDim.x + threadIdx.x) >> 5;
    int lane = threadIdx.x & 31;
    if (gw >= NN) return;
    const __half* __restrict__ H = g_h;
    float dv = g_dinv[gw];
    float sl = dv * dv;

    uint2 h0 = *(const uint2*)(H + (size_t)gw * 128 + lane * 4);
    float2 p0 = __half22float2(*(__half2*)&h0.x);
    float2 p1 = __half22float2(*(__half2*)&h0.y);
    float a0 = p0.x * sl, a1 = p0.y * sl, a2 = p1.x * sl, a3 = p1.y * sl;

    int e = g_off[gw], e1 = g_off[gw + 1];
    for (; e + 2 <= e1; e += 2) {
        int s0 = g_csr[e];
        int s1 = g_csr[e + 1];
        float n0 = dv * g_dinv[s0];
        float n1 = dv * g_dinv[s1];
        uint2 u0 = *(const uint2*)(H + (size_t)s0 * 128 + lane * 4);
        uint2 u1 = *(const uint2*)(H + (size_t)s1 * 128 + lane * 4);
        float2 q0 = __half22float2(*(__half2*)&u0.x);
        float2 q1 = __half22float2(*(__half2*)&u0.y);
        float2 r0 = __half22float2(*(__half2*)&u1.x);
        float2 r1 = __half22float2(*(__half2*)&u1.y);
        a0 += q0.x * n0 + r0.x * n1;
        a1 += q0.y * n0 + r0.y * n1;
        a2 += q1.x * n0 + r1.x * n1;
        a3 += q1.y * n0 + r1.y * n1;
    }
    if (e < e1) {
        int s = g_csr[e];
        float nm = dv * g_dinv[s];
        uint2 u = *(const uint2*)(H + (size_t)s * 128 + lane * 4);
        float2 q0 = __half22float2(*(__half2*)&u.x);
        float2 q1 = __half22float2(*(__half2*)&u.y);
        a0 += q0.x * nm; a1 += q0.y * nm; a2 += q1.x * nm; a3 += q1.y * nm;
    }
    float4 b = ((const float4*)b1)[lane];
    a0 = fmaxf(a0 + b.x, 0.f);
    a1 = fmaxf(a1 + b.y, 0.f);
    a2 = fmaxf(a2 + b.z, 0.f);
    a3 = fmaxf(a3 + b.w, 0.f);
    uint2 o;
    *(__half2*)&o.x = __floats2half2_rn(a0, a1);
    *(__half2*)&o.y = __floats2half2_rn(a2, a3);
    *(uint2*)(g_a + (size_t)gw * 128 + lane * 4) = o;
}

// ---------------- gather SpMM (layer 2): 64 cols fp16 in, fp32 out -------------
__global__ void spmm2(const float* __restrict__ b2, float* __restrict__ O) {
    int gw   = (blockIdx.x * blockDim.x + threadIdx.x) >> 5;
    int lane = threadIdx.x & 31;
    if (gw >= NN) return;
    const __half* __restrict__ T = g_t2;
    float dv = g_dinv[gw];
    float sl = dv * dv;

    float2 t0 = __half22float2(*(const __half2*)(T + (size_t)gw * 64 + lane * 2));
    float a0 = t0.x * sl, a1 = t0.y * sl;

    int e = g_off[gw], e1 = g_off[gw + 1];
    for (; e + 2 <= e1; e += 2) {
        int s0 = g_csr[e];
        int s1 = g_csr[e + 1];
        float n0 = dv * g_dinv[s0];
        float n1 = dv * g_dinv[s1];
        float2 v0 = __half22float2(*(const __half2*)(T + (size_t)s0 * 64 + lane * 2));
        float2 v1 = __half22float2(*(const __half2*)(T + (size_t)s1 * 64 + lane * 2));
        a0 += v0.x * n0 + v1.x * n1;
        a1 += v0.y * n0 + v1.y * n1;
    }
    if (e < e1) {
        int s = g_csr[e];
        float nm = dv * g_dinv[s];
        float2 v = __half22float2(*(const __half2*)(T + (size_t)s * 64 + lane * 2));
        a0 += v.x * nm;
        a1 += v.y * nm;
    }
    float2 b = ((const float2*)b2)[lane];
    ((float2*)O)[(size_t)gw * 32 + lane] = make_float2(a0 + b.x, a1 + b.y);
}

// ---------------- launch ---------------------------------------------------------
extern "C" void kernel_launch(void* const* d_in, const int* in_sizes, int n_in,
                              void* d_out, int out_size) {
    const float* x  = (const float*)d_in[0];
    const int*   ei = (const int*)d_in[1];     // int32 [2, E]
    const float* W1 = (const float*)d_in[2];
    const float* b1 = (const float*)d_in[3];
    const float* W2 = (const float*)d_in[4];
    const float* b2 = (const float*)d_in[5];
    float*       out = (float*)d_out;

    const int TB = 256;
    k_zero_cnt <<<(NN + TB - 1) / TB, TB>>>();
    k_count    <<<(EE + TB - 1) / TB, TB>>>(ei);
    k_scan_part<<<SCAN_BLOCKS, SCAN_CHUNK>>>();
    k_scan_base<<<1, 128>>>();
    k_scan_add <<<SCAN_BLOCKS, SCAN_CHUNK>>>();
    k_fill     <<<(EE + TB - 1) / TB, TB>>>(ei);

    const int GB = (NN + 127) / 128;   // 782
    // layer 1: g_h = x @ W1 ; g_a = relu(Ahat @ g_h + b1)
    gemm_k<128, 0><<<GB, 256>>>(x, W1);
    spmm1<<<(NN * 32 + TB - 1) / TB, TB>>>(b1);

    // layer 2: g_t2 = g_a @ W2 ; out = Ahat @ g_t2 + b2
    gemm_k<64, 1><<<GB, 256>>>(x /*unused*/, W2);
    spmm2<<<(NN * 32 + TB - 1) / TB, TB>>>(b2, out);
}

// round 10
// speedup vs baseline: 1.8241x; 1.4781x over previous
#include <cuda_runtime.h>
#include <cuda_fp16.h>
#include <cstdint>
#include <stdint.h>

// Problem constants (fixed shapes)
#define NN 100000
#define EE 1600000
#define SCAN_CHUNK 1024
#define SCAN_BLOCKS ((NN + SCAN_CHUNK - 1) / SCAN_CHUNK)   // 98

// ---------------- device scratch (static globals; no runtime alloc) -------------
__device__ int    g_cnt[NN];
__device__ int    g_off[NN + 1];
__device__ int    g_cur[NN];
__device__ int    g_part[SCAN_BLOCKS];
__device__ int    g_pbase[SCAN_BLOCKS];
__device__ float  g_dinv[NN];
__device__ int    g_csr[EE];
__device__ __half g_h  [NN * 128];   // x @ W1          (fp16 storage, fp32 acc)
__device__ __half g_a  [NN * 128];   // relu(Ahat@h+b1)
__device__ __half g_t2 [NN * 64];    // g_a @ W2
__device__ __half g_w1t[128 * 128];  // W1^T  [n][k] fp16 (k contiguous)
__device__ __half g_w2t[64 * 128];   // W2^T  [n][k] fp16

// ---------------- weight prep: transpose + fp16 convert -------------------------
__global__ void k_wprep(const float* __restrict__ W1, const float* __restrict__ W2) {
    int i = blockIdx.x * blockDim.x + threadIdx.x;
    if (i < 128 * 128) {
        int n = i >> 7, k = i & 127;
        g_w1t[i] = __float2half(W1[k * 128 + n]);
    }
    if (i < 64 * 128) {
        int n = i >> 7, k = i & 127;
        g_w2t[i] = __float2half(W2[k * 64 + n]);
    }
}

// ---------------- degree / CSR construction ------------------------------------
__global__ void k_zero_cnt() {
    int i = blockIdx.x * blockDim.x + threadIdx.x;
    if (i < NN) g_cnt[i] = 0;
}

// edge_index is INT32: layout [2, E] -> src = ei[e], dst = ei[E+e]
__global__ void k_count(const int* __restrict__ ei) {
    int e = blockIdx.x * blockDim.x + threadIdx.x;
    if (e < EE) atomicAdd(&g_cnt[ei[EE + e]], 1);
}

// phase 1: per-block exclusive scan into g_off; block total into g_part; also dinv
__global__ void k_scan_part() {
    __shared__ int warpsum[32];
    const int tid  = threadIdx.x;
    const int lane = tid & 31;
    const int wid  = tid >> 5;
    const int i = blockIdx.x * SCAN_CHUNK + tid;

    int v = (i < NN) ? g_cnt[i] : 0;
    if (i < NN) g_dinv[i] = rsqrtf((float)(v + 1));   // +1 self-loop
    int s = v;
    #pragma unroll
    for (int d = 1; d < 32; d <<= 1) {
        int t = __shfl_up_sync(0xffffffffu, s, d);
        if (lane >= d) s += t;
    }
    if (lane == 31) warpsum[wid] = s;
    __syncthreads();
    if (wid == 0) {
        int ws = warpsum[lane];
        #pragma unroll
        for (int d = 1; d < 32; d <<= 1) {
            int t = __shfl_up_sync(0xffffffffu, ws, d);
            if (lane >= d) ws += t;
        }
        warpsum[lane] = ws;
    }
    __syncthreads();
    int block_excl = (wid == 0) ? 0 : warpsum[wid - 1];
    if (i < NN) g_off[i] = s + block_excl - v;
    if (tid == SCAN_CHUNK - 1) g_part[blockIdx.x] = s + block_excl;
}

// phase 2: scan the 98 block totals
__global__ void k_scan_base() {
    __shared__ int sp[SCAN_BLOCKS];
    int tid = threadIdx.x;
    if (tid < SCAN_BLOCKS) sp[tid] = g_part[tid];
    __syncthreads();
    if (tid == 0) {
        int run = 0;
        for (int b = 0; b < SCAN_BLOCKS; ++b) { int t = sp[b]; sp[b] = run; run += t; }
        g_off[NN] = run;
    }
    __syncthreads();
    if (tid < SCAN_BLOCKS) g_pbase[tid] = sp[tid];
}

// phase 3: add block base; mirror into g_cur
__global__ void k_scan_add() {
    int i = blockIdx.x * SCAN_CHUNK + threadIdx.x;
    if (i < NN) {
        int o = g_off[i] + g_pbase[blockIdx.x];
        g_off[i] = o;
        g_cur[i] = o;
    }
}

__global__ void k_fill(const int* __restrict__ ei) {
    int e = blockIdx.x * blockDim.x + threadIdx.x;
    if (e < EE) {
        int d = ei[EE + e];
        int s = ei[e];
        g_csr[atomicAdd(&g_cur[d], 1)] = s;
    }
}

// ---------------- tensor-core helpers -------------------------------------------
__device__ __forceinline__ unsigned smem_u32(const void* p) {
    return (unsigned)__cvta_generic_to_shared(p);
}
__device__ __forceinline__ void ldsm_x4(unsigned& r0, unsigned& r1, unsigned& r2,
                                        unsigned& r3, unsigned addr) {
    asm volatile("ldmatrix.sync.aligned.m8n8.x4.shared.b16 {%0,%1,%2,%3}, [%4];"
                 : "=r"(r0), "=r"(r1), "=r"(r2), "=r"(r3) : "r"(addr));
}
__device__ __forceinline__ void ldsm_x2(unsigned& r0, unsigned& r1, unsigned addr) {
    asm volatile("ldmatrix.sync.aligned.m8n8.x2.shared.b16 {%0,%1}, [%2];"
                 : "=r"(r0), "=r"(r1) : "r"(addr));
}
__device__ __forceinline__ void mma16816(float& c0, float& c1, float& c2, float& c3,
                                         unsigned a0, unsigned a1, unsigned a2, unsigned a3,
                                         unsigned b0, unsigned b1) {
    asm volatile(
        "mma.sync.aligned.m16n8k16.row.col.f32.f16.f16.f32 "
        "{%0,%1,%2,%3}, {%4,%5,%6,%7}, {%8,%9}, {%0,%1,%2,%3};"
        : "+f"(c0), "+f"(c1), "+f"(c2), "+f"(c3)
        : "r"(a0), "r"(a1), "r"(a2), "r"(a3), "r"(b0), "r"(b1));
}

// ---------------- HMMA GEMM: C[NN x BN] = A[NN x 128] @ W[128 x BN], fp16 out ----
// Block tile 128 x BN, BK=32, 256 threads (8 warps).
// MODE 0: A = x (fp32 arg) -> g_h    (BN=128, WM=64, WN=32)
// MODE 1: A = g_a (fp16)   -> g_t2   (BN=64,  WM=32, WN=32)
#define SPITCH 40   // halves per smem row (conflict-free under ldmatrix)

template <int BN, int WM, int WN, int MODE>
__global__ __launch_bounds__(256) void hgemm(const float* __restrict__ Xf) {
    constexpr int MF = WM / 16;
    constexpr int NF = WN / 8;
    constexpr int NWN = BN / WN;

    __shared__ __half sA[128 * SPITCH];
    __shared__ __half sB[BN * SPITCH];

    const int t    = threadIdx.x;
    const int lane = t & 31;
    const int wid  = t >> 5;
    const int m_w  = (wid / NWN) * WM;
    const int n_w  = (wid % NWN) * WN;
    const int rowB = blockIdx.x * 128;

    __half* __restrict__ Ch = (MODE == 0) ? g_h : g_t2;
    const __half* __restrict__ Bt = (MODE == 0) ? g_w1t : g_w2t;
    const __half* __restrict__ Ah = g_a;

    float acc[MF][NF][4];
    #pragma unroll
    for (int i = 0; i < MF; ++i)
        #pragma unroll
        for (int j = 0; j < NF; ++j)
            #pragma unroll
            for (int q = 0; q < 4; ++q) acc[i][j][q] = 0.f;

    // loader indices: 2 threads per row, 16 halves each
    const int arow = t >> 1;
    const int asub = t & 1;

    #pragma unroll 1
    for (int kc = 0; kc < 4; ++kc) {
        const int k0 = kc * 32;
        // ---- load A tile: 128 rows x 32 halves
        {
            int gr = rowB + arow;
            uint4 u0, u1;
            if (MODE == 0) {
                float4 f0, f1, f2, f3;
                if (gr < NN) {
                    const float4* Xr = (const float4*)Xf + (size_t)gr * 32 + kc * 8 + asub * 4;
                    f0 = Xr[0]; f1 = Xr[1]; f2 = Xr[2]; f3 = Xr[3];
                } else {
                    f0 = f1 = f2 = f3 = make_float4(0.f, 0.f, 0.f, 0.f);
                }
                __half2 h0 = __floats2half2_rn(f0.x, f0.y), h1 = __floats2half2_rn(f0.z, f0.w);
                __half2 h2 = __floats2half2_rn(f1.x, f1.y), h3 = __floats2half2_rn(f1.z, f1.w);
                __half2 h4 = __floats2half2_rn(f2.x, f2.y), h5 = __floats2half2_rn(f2.z, f2.w);
                __half2 h6 = __floats2half2_rn(f3.x, f3.y), h7 = __floats2half2_rn(f3.z, f3.w);
                u0 = make_uint4(*(unsigned*)&h0, *(unsigned*)&h1, *(unsigned*)&h2, *(unsigned*)&h3);
                u1 = make_uint4(*(unsigned*)&h4, *(unsigned*)&h5, *(unsigned*)&h6, *(unsigned*)&h7);
            } else {
                if (gr < NN) {
                    const uint4* Ar = (const uint4*)(Ah + (size_t)gr * 128 + k0 + asub * 16);
                    u0 = Ar[0]; u1 = Ar[1];
                } else {
                    u0 = make_uint4(0u, 0u, 0u, 0u);
                    u1 = make_uint4(0u, 0u, 0u, 0u);
                }
            }
            uint4* dst = (uint4*)&sA[arow * SPITCH + asub * 16];
            dst[0] = u0; dst[1] = u1;
        }
        // ---- load B tile: BN rows x 32 halves (from pre-transposed fp16 weights)
        if (BN == 128 || t < 128) {
            int n = arow;            // for BN=64 only t<128 -> n<64
            const uint4* Br = (const uint4*)(Bt + (size_t)n * 128 + k0 + asub * 16);
            uint4* dst = (uint4*)&sB[n * SPITCH + asub * 16];
            dst[0] = Br[0]; dst[1] = Br[1];
        }
        __syncthreads();

        // ---- compute: 2 k16 steps
        #pragma unroll
        for (int ks = 0; ks < 2; ++ks) {
            unsigned af[MF][4];
            #pragma unroll
            for (int mf = 0; mf < MF; ++mf) {
                int r = m_w + mf * 16 + (lane & 15);
                int c = ks * 16 + ((lane >> 4) << 3);
                ldsm_x4(af[mf][0], af[mf][1], af[mf][2], af[mf][3],
                        smem_u32(&sA[r * SPITCH + c]));
            }
            unsigned bf[NF][2];
            #pragma unroll
            for (int nf = 0; nf < NF; ++nf) {
                int r = n_w + nf * 8 + (lane & 7);
                int c = ks * 16 + ((lane >> 3) & 1) * 8;
                ldsm_x2(bf[nf][0], bf[nf][1], smem_u32(&sB[r * SPITCH + c]));
            }
            #pragma unroll
            for (int mf = 0; mf < MF; ++mf)
                #pragma unroll
                for (int nf = 0; nf < NF; ++nf)
                    mma16816(acc[mf][nf][0], acc[mf][nf][1], acc[mf][nf][2], acc[mf][nf][3],
                             af[mf][0], af[mf][1], af[mf][2], af[mf][3],
                             bf[nf][0], bf[nf][1]);
        }
        __syncthreads();
    }

    // ---- epilogue: fp16 store
    #pragma unroll
    for (int mf = 0; mf < MF; ++mf) {
        int m0 = rowB + m_w + mf * 16 + (lane >> 2);
        #pragma unroll
        for (int nf = 0; nf < NF; ++nf) {
            int n = n_w + nf * 8 + (lane & 3) * 2;
            if (m0 < NN) {
                __half2 p = __floats2half2_rn(acc[mf][nf][0], acc[mf][nf][1]);
                *(__half2*)(Ch + (size_t)m0 * BN + n) = p;
            }
            if (m0 + 8 < NN) {
                __half2 p = __floats2half2_rn(acc[mf][nf][2], acc[mf][nf][3]);
                *(__half2*)(Ch + (size_t)(m0 + 8) * BN + n) = p;
            }
        }
    }
}

// ---------------- gather SpMM (layer 1): 128 cols fp16, one warp per node ------
__global__ void spmm1(const float* __restrict__ b1) {
    int gw   = (blockIdx.x * blockDim.x + threadIdx.x) >> 5;
    int lane = threadIdx.x & 31;
    if (gw >= NN) return;
    const __half* __restrict__ H = g_h;
    float dv = g_dinv[gw];
    float sl = dv * dv;

    uint2 h0 = *(const uint2*)(H + (size_t)gw * 128 + lane * 4);
    float2 p0 = __half22float2(*(__half2*)&h0.x);
    float2 p1 = __half22float2(*(__half2*)&h0.y);
    float a0 = p0.x * sl, a1 = p0.y * sl, a2 = p1.x * sl, a3 = p1.y * sl;

    int e = g_off[gw], e1 = g_off[gw + 1];
    for (; e + 2 <= e1; e += 2) {
        int s0 = g_csr[e];
        int s1 = g_csr[e + 1];
        float n0 = dv * g_dinv[s0];
        float n1 = dv * g_dinv[s1];
        uint2 u0 = *(const uint2*)(H + (size_t)s0 * 128 + lane * 4);
        uint2 u1 = *(const uint2*)(H + (size_t)s1 * 128 + lane * 4);
        float2 q0 = __half22float2(*(__half2*)&u0.x);
        float2 q1 = __half22float2(*(__half2*)&u0.y);
        float2 r0 = __half22float2(*(__half2*)&u1.x);
        float2 r1 = __half22float2(*(__half2*)&u1.y);
        a0 += q0.x * n0 + r0.x * n1;
        a1 += q0.y * n0 + r0.y * n1;
        a2 += q1.x * n0 + r1.x * n1;
        a3 += q1.y * n0 + r1.y * n1;
    }
    if (e < e1) {
        int s = g_csr[e];
        float nm = dv * g_dinv[s];
        uint2 u = *(const uint2*)(H + (size_t)s * 128 + lane * 4);
        float2 q0 = __half22float2(*(__half2*)&u.x);
        float2 q1 = __half22float2(*(__half2*)&u.y);
        a0 += q0.x * nm; a1 += q0.y * nm; a2 += q1.x * nm; a3 += q1.y * nm;
    }
    float4 b = ((const float4*)b1)[lane];
    a0 = fmaxf(a0 + b.x, 0.f);
    a1 = fmaxf(a1 + b.y, 0.f);
    a2 = fmaxf(a2 + b.z, 0.f);
    a3 = fmaxf(a3 + b.w, 0.f);
    uint2 o;
    *(__half2*)&o.x = __floats2half2_rn(a0, a1);
    *(__half2*)&o.y = __floats2half2_rn(a2, a3);
    *(uint2*)(g_a + (size_t)gw * 128 + lane * 4) = o;
}

// ---------------- gather SpMM (layer 2): 64 cols fp16 in, fp32 out -------------
__global__ void spmm2(const float* __restrict__ b2, float* __restrict__ O) {
    int gw   = (blockIdx.x * blockDim.x + threadIdx.x) >> 5;
    int lane = threadIdx.x & 31;
    if (gw >= NN) return;
    const __half* __restrict__ T = g_t2;
    float dv = g_dinv[gw];
    float sl = dv * dv;

    float2 t0 = __half22float2(*(const __half2*)(T + (size_t)gw * 64 + lane * 2));
    float a0 = t0.x * sl, a1 = t0.y * sl;

    int e = g_off[gw], e1 = g_off[gw + 1];
    for (; e + 2 <= e1; e += 2) {
        int s0 = g_csr[e];
        int s1 = g_csr[e + 1];
        float n0 = dv * g_dinv[s0];
        float n1 = dv * g_dinv[s1];
        float2 v0 = __half22float2(*(const __half2*)(T + (size_t)s0 * 64 + lane * 2));
        float2 v1 = __half22float2(*(const __half2*)(T + (size_t)s1 * 64 + lane * 2));
        a0 += v0.x * n0 + v1.x * n1;
        a1 += v0.y * n0 + v1.y * n1;
    }
    if (e < e1) {
        int s = g_csr[e];
        float nm = dv * g_dinv[s];
        float2 v = __half22float2(*(const __half2*)(T + (size_t)s * 64 + lane * 2));
        a0 += v.x * nm;
        a1 += v.y * nm;
    }
    float2 b = ((const float2*)b2)[lane];
    ((float2*)O)[(size_t)gw * 32 + lane] = make_float2(a0 + b.x, a1 + b.y);
}

// ---------------- launch ---------------------------------------------------------
extern "C" void kernel_launch(void* const* d_in, const int* in_sizes, int n_in,
                              void* d_out, int out_size) {
    const float* x  = (const float*)d_in[0];
    const int*   ei = (const int*)d_in[1];     // int32 [2, E]
    const float* W1 = (const float*)d_in[2];
    const float* b1 = (const float*)d_in[3];
    const float* W2 = (const float*)d_in[4];
    const float* b2 = (const float*)d_in[5];
    float*       out = (float*)d_out;

    const int TB = 256;
    k_wprep    <<<64, 256>>>(W1, W2);
    k_zero_cnt <<<(NN + TB - 1) / TB, TB>>>();
    k_count    <<<(EE + TB - 1) / TB, TB>>>(ei);
    k_scan_part<<<SCAN_BLOCKS, SCAN_CHUNK>>>();
    k_scan_base<<<1, 128>>>();
    k_scan_add <<<SCAN_BLOCKS, SCAN_CHUNK>>>();
    k_fill     <<<(EE + TB - 1) / TB, TB>>>(ei);

    const int GB = (NN + 127) / 128;   // 782
    // layer 1: g_h = x @ W1 ; g_a = relu(Ahat @ g_h + b1)
    hgemm<128, 64, 32, 0><<<GB, 256>>>(x);
    spmm1<<<(NN * 32 + TB - 1) / TB, TB>>>(b1);

    // layer 2: g_t2 = g_a @ W2 ; out = Ahat @ g_t2 + b2
    hgemm<64, 32, 32, 1><<<GB, 256>>>(x /*unused*/);
    spmm2<<<(NN * 32 + TB - 1) / TB, TB>>>(b2, out);
}

// round 11
// speedup vs baseline: 2.0651x; 1.1321x over previous
#include <cuda_runtime.h>
#include <cuda_fp16.h>
#include <cstdint>
#include <stdint.h>

// Problem constants (fixed shapes)
#define NN 100000
#define EE 1600000
#define SCAN_CHUNK 1024
#define SCAN_BLOCKS ((NN + SCAN_CHUNK - 1) / SCAN_CHUNK)   // 98

// ---------------- device scratch (static globals; no runtime alloc) -------------
__device__ int    g_cnt[NN];
__device__ int    g_off[NN + 1];
__device__ int    g_cur[NN];
__device__ int    g_part[SCAN_BLOCKS];
__device__ int    g_pbase[SCAN_BLOCKS];
__device__ float  g_dinv[NN];
__device__ int    g_csr[EE];
__device__ __half g_h  [NN * 128];   // dinv * (x @ W1)      (pre-scaled rows)
__device__ __half g_a  [NN * 128];   // relu(Ahat@h+b1)
__device__ __half g_t2 [NN * 64];    // dinv * (g_a @ W2)    (pre-scaled rows)
__device__ __half g_w1t[128 * 128];  // W1^T  [n][k] fp16 (k contiguous)
__device__ __half g_w2t[64 * 128];   // W2^T  [n][k] fp16

// ---------------- weight prep: transpose + fp16 convert -------------------------
__global__ void k_wprep(const float* __restrict__ W1, const float* __restrict__ W2) {
    int i = blockIdx.x * blockDim.x + threadIdx.x;
    if (i < 128 * 128) {
        int n = i >> 7, k = i & 127;
        g_w1t[i] = __float2half(W1[k * 128 + n]);
    }
    if (i < 64 * 128) {
        int n = i >> 7, k = i & 127;
        g_w2t[i] = __float2half(W2[k * 64 + n]);
    }
}

// ---------------- degree / CSR construction ------------------------------------
__global__ void k_zero_cnt() {
    int i = blockIdx.x * blockDim.x + threadIdx.x;
    if (i < NN) g_cnt[i] = 0;
}

// edge_index is INT32: layout [2, E] -> src = ei[e], dst = ei[E+e]
__global__ void k_count(const int* __restrict__ ei) {
    int e = blockIdx.x * blockDim.x + threadIdx.x;
    if (e < EE) atomicAdd(&g_cnt[ei[EE + e]], 1);
}

// phase 1: per-block exclusive scan into g_off; block total into g_part; also dinv
__global__ void k_scan_part() {
    __shared__ int warpsum[32];
    const int tid  = threadIdx.x;
    const int lane = tid & 31;
    const int wid  = tid >> 5;
    const int i = blockIdx.x * SCAN_CHUNK + tid;

    int v = (i < NN) ? g_cnt[i] : 0;
    if (i < NN) g_dinv[i] = rsqrtf((float)(v + 1));   // +1 self-loop
    int s = v;
    #pragma unroll
    for (int d = 1; d < 32; d <<= 1) {
        int t = __shfl_up_sync(0xffffffffu, s, d);
        if (lane >= d) s += t;
    }
    if (lane == 31) warpsum[wid] = s;
    __syncthreads();
    if (wid == 0) {
        int ws = warpsum[lane];
        #pragma unroll
        for (int d = 1; d < 32; d <<= 1) {
            int t = __shfl_up_sync(0xffffffffu, ws, d);
            if (lane >= d) ws += t;
        }
        warpsum[lane] = ws;
    }
    __syncthreads();
    int block_excl = (wid == 0) ? 0 : warpsum[wid - 1];
    if (i < NN) g_off[i] = s + block_excl - v;
    if (tid == SCAN_CHUNK - 1) g_part[blockIdx.x] = s + block_excl;
}

// phase 2: scan the 98 block totals
__global__ void k_scan_base() {
    __shared__ int sp[SCAN_BLOCKS];
    int tid = threadIdx.x;
    if (tid < SCAN_BLOCKS) sp[tid] = g_part[tid];
    __syncthreads();
    if (tid == 0) {
        int run = 0;
        for (int b = 0; b < SCAN_BLOCKS; ++b) { int t = sp[b]; sp[b] = run; run += t; }
        g_off[NN] = run;
    }
    __syncthreads();
    if (tid < SCAN_BLOCKS) g_pbase[tid] = sp[tid];
}

// phase 3: add block base; mirror into g_cur
__global__ void k_scan_add() {
    int i = blockIdx.x * SCAN_CHUNK + threadIdx.x;
    if (i < NN) {
        int o = g_off[i] + g_pbase[blockIdx.x];
        g_off[i] = o;
        g_cur[i] = o;
    }
}

__global__ void k_fill(const int* __restrict__ ei) {
    int e = blockIdx.x * blockDim.x + threadIdx.x;
    if (e < EE) {
        int d = ei[EE + e];
        int s = ei[e];
        g_csr[atomicAdd(&g_cur[d], 1)] = s;
    }
}

// ---------------- tensor-core helpers -------------------------------------------
__device__ __forceinline__ unsigned smem_u32(const void* p) {
    return (unsigned)__cvta_generic_to_shared(p);
}
__device__ __forceinline__ void ldsm_x4(unsigned& r0, unsigned& r1, unsigned& r2,
                                        unsigned& r3, unsigned addr) {
    asm volatile("ldmatrix.sync.aligned.m8n8.x4.shared.b16 {%0,%1,%2,%3}, [%4];"
                 : "=r"(r0), "=r"(r1), "=r"(r2), "=r"(r3) : "r"(addr));
}
__device__ __forceinline__ void ldsm_x2(unsigned& r0, unsigned& r1, unsigned addr) {
    asm volatile("ldmatrix.sync.aligned.m8n8.x2.shared.b16 {%0,%1}, [%2];"
                 : "=r"(r0), "=r"(r1) : "r"(addr));
}
__device__ __forceinline__ void mma16816(float& c0, float& c1, float& c2, float& c3,
                                         unsigned a0, unsigned a1, unsigned a2, unsigned a3,
                                         unsigned b0, unsigned b1) {
    asm volatile(
        "mma.sync.aligned.m16n8k16.row.col.f32.f16.f16.f32 "
        "{%0,%1,%2,%3}, {%4,%5,%6,%7}, {%8,%9}, {%0,%1,%2,%3};"
        : "+f"(c0), "+f"(c1), "+f"(c2), "+f"(c3)
        : "r"(a0), "r"(a1), "r"(a2), "r"(a3), "r"(b0), "r"(b1));
}

// ---------------- HMMA GEMM: C[m] = dinv[m] * (A[m] @ W), fp16 out ---------------
// Block tile 128 x BN, BK=32, 256 threads (8 warps).
// MODE 0: A = x (fp32 arg) -> g_h    (BN=128, WM=64, WN=32)
// MODE 1: A = g_a (fp16)   -> g_t2   (BN=64,  WM=32, WN=32)
#define SPITCH 40   // halves per smem row (conflict-free under ldmatrix)

template <int BN, int WM, int WN, int MODE>
__global__ __launch_bounds__(256) void hgemm(const float* __restrict__ Xf) {
    constexpr int MF = WM / 16;
    constexpr int NF = WN / 8;
    constexpr int NWN = BN / WN;

    __shared__ __half sA[128 * SPITCH];
    __shared__ __half sB[BN * SPITCH];

    const int t    = threadIdx.x;
    const int lane = t & 31;
    const int wid  = t >> 5;
    const int m_w  = (wid / NWN) * WM;
    const int n_w  = (wid % NWN) * WN;
    const int rowB = blockIdx.x * 128;

    __half* __restrict__ Ch = (MODE == 0) ? g_h : g_t2;
    const __half* __restrict__ Bt = (MODE == 0) ? g_w1t : g_w2t;
    const __half* __restrict__ Ah = g_a;

    float acc[MF][NF][4];
    #pragma unroll
    for (int i = 0; i < MF; ++i)
        #pragma unroll
        for (int j = 0; j < NF; ++j)
            #pragma unroll
            for (int q = 0; q < 4; ++q) acc[i][j][q] = 0.f;

    // loader indices: 2 threads per row, 16 halves each
    const int arow = t >> 1;
    const int asub = t & 1;

    #pragma unroll 1
    for (int kc = 0; kc < 4; ++kc) {
        const int k0 = kc * 32;
        // ---- load A tile: 128 rows x 32 halves
        {
            int gr = rowB + arow;
            uint4 u0, u1;
            if (MODE == 0) {
                float4 f0, f1, f2, f3;
                if (gr < NN) {
                    const float4* Xr = (const float4*)Xf + (size_t)gr * 32 + kc * 8 + asub * 4;
                    f0 = Xr[0]; f1 = Xr[1]; f2 = Xr[2]; f3 = Xr[3];
                } else {
                    f0 = f1 = f2 = f3 = make_float4(0.f, 0.f, 0.f, 0.f);
                }
                __half2 h0 = __floats2half2_rn(f0.x, f0.y), h1 = __floats2half2_rn(f0.z, f0.w);
                __half2 h2 = __floats2half2_rn(f1.x, f1.y), h3 = __floats2half2_rn(f1.z, f1.w);
                __half2 h4 = __floats2half2_rn(f2.x, f2.y), h5 = __floats2half2_rn(f2.z, f2.w);
                __half2 h6 = __floats2half2_rn(f3.x, f3.y), h7 = __floats2half2_rn(f3.z, f3.w);
                u0 = make_uint4(*(unsigned*)&h0, *(unsigned*)&h1, *(unsigned*)&h2, *(unsigned*)&h3);
                u1 = make_uint4(*(unsigned*)&h4, *(unsigned*)&h5, *(unsigned*)&h6, *(unsigned*)&h7);
            } else {
                if (gr < NN) {
                    const uint4* Ar = (const uint4*)(Ah + (size_t)gr * 128 + k0 + asub * 16);
                    u0 = Ar[0]; u1 = Ar[1];
                } else {
                    u0 = make_uint4(0u, 0u, 0u, 0u);
                    u1 = make_uint4(0u, 0u, 0u, 0u);
                }
            }
            uint4* dst = (uint4*)&sA[arow * SPITCH + asub * 16];
            dst[0] = u0; dst[1] = u1;
        }
        // ---- load B tile: BN rows x 32 halves (from pre-transposed fp16 weights)
        if (BN == 128 || t < 128) {
            int n = arow;            // for BN=64 only t<128 -> n<64
            const uint4* Br = (const uint4*)(Bt + (size_t)n * 128 + k0 + asub * 16);
            uint4* dst = (uint4*)&sB[n * SPITCH + asub * 16];
            dst[0] = Br[0]; dst[1] = Br[1];
        }
        __syncthreads();

        // ---- compute: 2 k16 steps
        #pragma unroll
        for (int ks = 0; ks < 2; ++ks) {
            unsigned af[MF][4];
            #pragma unroll
            for (int mf = 0; mf < MF; ++mf) {
                int r = m_w + mf * 16 + (lane & 15);
                int c = ks * 16 + ((lane >> 4) << 3);
                ldsm_x4(af[mf][0], af[mf][1], af[mf][2], af[mf][3],
                        smem_u32(&sA[r * SPITCH + c]));
            }
            unsigned bf[NF][2];
            #pragma unroll
            for (int nf = 0; nf < NF; ++nf) {
                int r = n_w + nf * 8 + (lane & 7);
                int c = ks * 16 + ((lane >> 3) & 1) * 8;
                ldsm_x2(bf[nf][0], bf[nf][1], smem_u32(&sB[r * SPITCH + c]));
            }
            #pragma unroll
            for (int mf = 0; mf < MF; ++mf)
                #pragma unroll
                for (int nf = 0; nf < NF; ++nf)
                    mma16816(acc[mf][nf][0], acc[mf][nf][1], acc[mf][nf][2], acc[mf][nf][3],
                             af[mf][0], af[mf][1], af[mf][2], af[mf][3],
                             bf[nf][0], bf[nf][1]);
        }
        __syncthreads();
    }

    // ---- epilogue: scale row m by dinv[m], store fp16
    #pragma unroll
    for (int mf = 0; mf < MF; ++mf) {
        int m0 = rowB + m_w + mf * 16 + (lane >> 2);
        float d0 = (m0     < NN) ? g_dinv[m0]     : 0.f;
        float d1 = (m0 + 8 < NN) ? g_dinv[m0 + 8] : 0.f;
        #pragma unroll
        for (int nf = 0; nf < NF; ++nf) {
            int n = n_w + nf * 8 + (lane & 3) * 2;
            if (m0 < NN) {
                __half2 p = __floats2half2_rn(acc[mf][nf][0] * d0, acc[mf][nf][1] * d0);
                *(__half2*)(Ch + (size_t)m0 * BN + n) = p;
            }
            if (m0 + 8 < NN) {
                __half2 p = __floats2half2_rn(acc[mf][nf][2] * d1, acc[mf][nf][3] * d1);
                *(__half2*)(Ch + (size_t)(m0 + 8) * BN + n) = p;
            }
        }
    }
}

// ---------------- gather SpMM (layer 1): 128 cols fp16, one warp per node ------
// g_h rows are pre-scaled by dinv[src]; result = relu(dinv[d]*(sum + self) + b1).
__global__ void spmm1(const float* __restrict__ b1) {
    int gw   = (blockIdx.x * blockDim.x + threadIdx.x) >> 5;
    int lane = threadIdx.x & 31;
    if (gw >= NN) return;
    const __half* __restrict__ H = g_h;
    float dv = g_dinv[gw];

    uint2 h0 = *(const uint2*)(H + (size_t)gw * 128 + lane * 4);
    float2 p0 = __half22float2(*(__half2*)&h0.x);
    float2 p1 = __half22float2(*(__half2*)&h0.y);
    float a0 = p0.x, a1 = p0.y, a2 = p1.x, a3 = p1.y;

    int e = g_off[gw], e1 = g_off[gw + 1];
    for (; e + 4 <= e1; e += 4) {
        int s0 = g_csr[e];
        int s1 = g_csr[e + 1];
        int s2 = g_csr[e + 2];
        int s3 = g_csr[e + 3];
        uint2 u0 = *(const uint2*)(H + (size_t)s0 * 128 + lane * 4);
        uint2 u1 = *(const uint2*)(H + (size_t)s1 * 128 + lane * 4);
        uint2 u2 = *(const uint2*)(H + (size_t)s2 * 128 + lane * 4);
        uint2 u3 = *(const uint2*)(H + (size_t)s3 * 128 + lane * 4);
        float2 q0 = __half22float2(*(__half2*)&u0.x), q1 = __half22float2(*(__half2*)&u0.y);
        float2 r0 = __half22float2(*(__half2*)&u1.x), r1 = __half22float2(*(__half2*)&u1.y);
        float2 w0 = __half22float2(*(__half2*)&u2.x), w1 = __half22float2(*(__half2*)&u2.y);
        float2 z0 = __half22float2(*(__half2*)&u3.x), z1 = __half22float2(*(__half2*)&u3.y);
        a0 += (q0.x + r0.x) + (w0.x + z0.x);
        a1 += (q0.y + r0.y) + (w0.y + z0.y);
        a2 += (q1.x + r1.x) + (w1.x + z1.x);
        a3 += (q1.y + r1.y) + (w1.y + z1.y);
    }
    for (; e < e1; ++e) {
        int s = g_csr[e];
        uint2 u = *(const uint2*)(H + (size_t)s * 128 + lane * 4);
        float2 q0 = __half22float2(*(__half2*)&u.x);
        float2 q1 = __half22float2(*(__half2*)&u.y);
        a0 += q0.x; a1 += q0.y; a2 += q1.x; a3 += q1.y;
    }
    float4 b = ((const float4*)b1)[lane];
    a0 = fmaxf(a0 * dv + b.x, 0.f);
    a1 = fmaxf(a1 * dv + b.y, 0.f);
    a2 = fmaxf(a2 * dv + b.z, 0.f);
    a3 = fmaxf(a3 * dv + b.w, 0.f);
    uint2 o;
    *(__half2*)&o.x = __floats2half2_rn(a0, a1);
    *(__half2*)&o.y = __floats2half2_rn(a2, a3);
    *(uint2*)(g_a + (size_t)gw * 128 + lane * 4) = o;
}

// ---------------- gather SpMM (layer 2): 64 cols fp16 in, fp32 out -------------
// g_t2 rows pre-scaled by dinv[src]; out = dinv[d]*(sum + self) + b2.
__global__ void spmm2(const float* __restrict__ b2, float* __restrict__ O) {
    int gw   = (blockIdx.x * blockDim.x + threadIdx.x) >> 5;
    int lane = threadIdx.x & 31;
    if (gw >= NN) return;
    const __half* __restrict__ T = g_t2;
    float dv = g_dinv[gw];

    float2 t0 = __half22float2(*(const __half2*)(T + (size_t)gw * 64 + lane * 2));
    float a0 = t0.x, a1 = t0.y;

    int e = g_off[gw], e1 = g_off[gw + 1];
    for (; e + 4 <= e1; e += 4) {
        int s0 = g_csr[e];
        int s1 = g_csr[e + 1];
        int s2 = g_csr[e + 2];
        int s3 = g_csr[e + 3];
        float2 v0 = __half22float2(*(const __half2*)(T + (size_t)s0 * 64 + lane * 2));
        float2 v1 = __half22float2(*(const __half2*)(T + (size_t)s1 * 64 + lane * 2));
        float2 v2 = __half22float2(*(const __half2*)(T + (size_t)s2 * 64 + lane * 2));
        float2 v3 = __half22float2(*(const __half2*)(T + (size_t)s3 * 64 + lane * 2));
        a0 += (v0.x + v1.x) + (v2.x + v3.x);
        a1 += (v0.y + v1.y) + (v2.y + v3.y);
    }
    for (; e < e1; ++e) {
        int s = g_csr[e];
        float2 v = __half22float2(*(const __half2*)(T + (size_t)s * 64 + lane * 2));
        a0 += v.x;
        a1 += v.y;
    }
    float2 b = ((const float2*)b2)[lane];
    ((float2*)O)[(size_t)gw * 32 + lane] = make_float2(a0 * dv + b.x, a1 * dv + b.y);
}

// ---------------- launch ---------------------------------------------------------
extern "C" void kernel_launch(void* const* d_in, const int* in_sizes, int n_in,
                              void* d_out, int out_size) {
    const float* x  = (const float*)d_in[0];
    const int*   ei = (const int*)d_in[1];     // int32 [2, E]
    const float* W1 = (const float*)d_in[2];
    const float* b1 = (const float*)d_in[3];
    const float* W2 = (const float*)d_in[4];
    const float* b2 = (const float*)d_in[5];
    float*       out = (float*)d_out;

    const int TB = 256;
    k_wprep    <<<64, 256>>>(W1, W2);
    k_zero_cnt <<<(NN + TB - 1) / TB, TB>>>();
    k_count    <<<(EE + TB - 1) / TB, TB>>>(ei);
    k_scan_part<<<SCAN_BLOCKS, SCAN_CHUNK>>>();
    k_scan_base<<<1, 128>>>();
    k_scan_add <<<SCAN_BLOCKS, SCAN_CHUNK>>>();
    k_fill     <<<(EE + TB - 1) / TB, TB>>>(ei);

    const int GB = (NN + 127) / 128;   // 782
    // layer 1: g_h = dinv*(x @ W1) ; g_a = relu(dinv*(sum h') + b1)
    hgemm<128, 64, 32, 0><<<GB, 256>>>(x);
    spmm1<<<(NN * 32 + TB - 1) / TB, TB>>>(b1);

    // layer 2: g_t2 = dinv*(g_a @ W2) ; out = dinv*(sum t2') + b2
    hgemm<64, 32, 32, 1><<<GB, 256>>>(x /*unused*/);
    spmm2<<<(NN * 32 + TB - 1) / TB, TB>>>(b2, out);
}

// round 12
// speedup vs baseline: 2.2175x; 1.0738x over previous
#include <cuda_runtime.h>
#include <cuda_fp16.h>
#include <cstdint>
#include <stdint.h>

// Problem constants (fixed shapes)
#define NN 100000
#define EE 1600000
#define SCAN_CHUNK 1024
#define SCAN_BLOCKS ((NN + SCAN_CHUNK - 1) / SCAN_CHUNK)   // 98

// ---------------- device scratch (static globals; no runtime alloc) -------------
__device__ int    g_cnt[NN];
__device__ int    g_off[NN + 1];
__device__ int    g_cur[NN];
__device__ int    g_part[SCAN_BLOCKS];
__device__ int    g_pbase[SCAN_BLOCKS];
__device__ float  g_dinv[NN];
__device__ int    g_csr[EE];
__device__ __half g_h  [NN * 128];   // dinv * (x @ W1)      (pre-scaled rows)
__device__ __half g_a  [NN * 128];   // relu(Ahat@h+b1)
__device__ __half g_t2 [NN * 64];    // dinv * (g_a @ W2)    (pre-scaled rows)
__device__ __half g_w1t[128 * 128];  // W1^T  [n][k] fp16 (k contiguous)
__device__ __half g_w2t[64 * 128];   // W2^T  [n][k] fp16

// ---------------- weight prep: transpose + fp16 convert -------------------------
__global__ void k_wprep(const float* __restrict__ W1, const float* __restrict__ W2) {
    int i = blockIdx.x * blockDim.x + threadIdx.x;
    if (i < 128 * 128) {
        int n = i >> 7, k = i & 127;
        g_w1t[i] = __float2half(W1[k * 128 + n]);
    }
    if (i < 64 * 128) {
        int n = i >> 7, k = i & 127;
        g_w2t[i] = __float2half(W2[k * 64 + n]);
    }
}

// ---------------- degree / CSR construction ------------------------------------
__global__ void k_zero_cnt() {
    int i = blockIdx.x * blockDim.x + threadIdx.x;
    if (i < NN) g_cnt[i] = 0;
}

// edge_index is INT32: layout [2, E] -> src = ei[e], dst = ei[E+e]
__global__ void k_count(const int* __restrict__ ei) {
    int e = blockIdx.x * blockDim.x + threadIdx.x;
    if (e < EE) atomicAdd(&g_cnt[ei[EE + e]], 1);
}

// phase 1: per-block exclusive scan into g_off; block total into g_part; also dinv
__global__ void k_scan_part() {
    __shared__ int warpsum[32];
    const int tid  = threadIdx.x;
    const int lane = tid & 31;
    const int wid  = tid >> 5;
    const int i = blockIdx.x * SCAN_CHUNK + tid;

    int v = (i < NN) ? g_cnt[i] : 0;
    if (i < NN) g_dinv[i] = rsqrtf((float)(v + 1));   // +1 self-loop
    int s = v;
    #pragma unroll
    for (int d = 1; d < 32; d <<= 1) {
        int t = __shfl_up_sync(0xffffffffu, s, d);
        if (lane >= d) s += t;
    }
    if (lane == 31) warpsum[wid] = s;
    __syncthreads();
    if (wid == 0) {
        int ws = warpsum[lane];
        #pragma unroll
        for (int d = 1; d < 32; d <<= 1) {
            int t = __shfl_up_sync(0xffffffffu, ws, d);
            if (lane >= d) ws += t;
        }
        warpsum[lane] = ws;
    }
    __syncthreads();
    int block_excl = (wid == 0) ? 0 : warpsum[wid - 1];
    if (i < NN) g_off[i] = s + block_excl - v;
    if (tid == SCAN_CHUNK - 1) g_part[blockIdx.x] = s + block_excl;
}

// phase 2: scan the 98 block totals
__global__ void k_scan_base() {
    __shared__ int sp[SCAN_BLOCKS];
    int tid = threadIdx.x;
    if (tid < SCAN_BLOCKS) sp[tid] = g_part[tid];
    __syncthreads();
    if (tid == 0) {
        int run = 0;
        for (int b = 0; b < SCAN_BLOCKS; ++b) { int t = sp[b]; sp[b] = run; run += t; }
        g_off[NN] = run;
    }
    __syncthreads();
    if (tid < SCAN_BLOCKS) g_pbase[tid] = sp[tid];
}

// phase 3: add block base; mirror into g_cur
__global__ void k_scan_add() {
    int i = blockIdx.x * SCAN_CHUNK + threadIdx.x;
    if (i < NN) {
        int o = g_off[i] + g_pbase[blockIdx.x];
        g_off[i] = o;
        g_cur[i] = o;
    }
}

__global__ void k_fill(const int* __restrict__ ei) {
    int e = blockIdx.x * blockDim.x + threadIdx.x;
    if (e < EE) {
        int d = ei[EE + e];
        int s = ei[e];
        g_csr[atomicAdd(&g_cur[d], 1)] = s;
    }
}

// ---------------- tensor-core helpers -------------------------------------------
__device__ __forceinline__ unsigned smem_u32(const void* p) {
    return (unsigned)__cvta_generic_to_shared(p);
}
__device__ __forceinline__ void ldsm_x4(unsigned& r0, unsigned& r1, unsigned& r2,
                                        unsigned& r3, unsigned addr) {
    asm volatile("ldmatrix.sync.aligned.m8n8.x4.shared.b16 {%0,%1,%2,%3}, [%4];"
                 : "=r"(r0), "=r"(r1), "=r"(r2), "=r"(r3) : "r"(addr));
}
__device__ __forceinline__ void ldsm_x2(unsigned& r0, unsigned& r1, unsigned addr) {
    asm volatile("ldmatrix.sync.aligned.m8n8.x2.shared.b16 {%0,%1}, [%2];"
                 : "=r"(r0), "=r"(r1) : "r"(addr));
}
__device__ __forceinline__ void mma16816(float& c0, float& c1, float& c2, float& c3,
                                         unsigned a0, unsigned a1, unsigned a2, unsigned a3,
                                         unsigned b0, unsigned b1) {
    asm volatile(
        "mma.sync.aligned.m16n8k16.row.col.f32.f16.f16.f32 "
        "{%0,%1,%2,%3}, {%4,%5,%6,%7}, {%8,%9}, {%0,%1,%2,%3};"
        : "+f"(c0), "+f"(c1), "+f"(c2), "+f"(c3)
        : "r"(a0), "r"(a1), "r"(a2), "r"(a3), "r"(b0), "r"(b1));
}

// ---------------- HMMA GEMM: C[m] = dinv[m] * (A[m] @ W), fp16 out ---------------
// Block tile 128 x BN, BK=32, 256 threads (8 warps).
// MODE 0: A = x (fp32 arg) -> g_h    (BN=128, WM=64, WN=32)
// MODE 1: A = g_a (fp16)   -> g_t2   (BN=64,  WM=32, WN=32)
#define SPITCH 40   // halves per smem row (conflict-free under ldmatrix)

template <int BN, int WM, int WN, int MODE>
__global__ __launch_bounds__(256) void hgemm(const float* __restrict__ Xf) {
    constexpr int MF = WM / 16;
    constexpr int NF = WN / 8;
    constexpr int NWN = BN / WN;

    __shared__ __half sA[128 * SPITCH];
    __shared__ __half sB[BN * SPITCH];

    const int t    = threadIdx.x;
    const int lane = t & 31;
    const int wid  = t >> 5;
    const int m_w  = (wid / NWN) * WM;
    const int n_w  = (wid % NWN) * WN;
    const int rowB = blockIdx.x * 128;

    __half* __restrict__ Ch = (MODE == 0) ? g_h : g_t2;
    const __half* __restrict__ Bt = (MODE == 0) ? g_w1t : g_w2t;
    const __half* __restrict__ Ah = g_a;

    float acc[MF][NF][4];
    #pragma unroll
    for (int i = 0; i < MF; ++i)
        #pragma unroll
        for (int j = 0; j < NF; ++j)
            #pragma unroll
            for (int q = 0; q < 4; ++q) acc[i][j][q] = 0.f;

    // loader indices: 2 threads per row, 16 halves each
    const int arow = t >> 1;
    const int asub = t & 1;

    #pragma unroll 1
    for (int kc = 0; kc < 4; ++kc) {
        const int k0 = kc * 32;
        // ---- load A tile: 128 rows x 32 halves
        {
            int gr = rowB + arow;
            uint4 u0, u1;
            if (MODE == 0) {
                float4 f0, f1, f2, f3;
                if (gr < NN) {
                    const float4* Xr = (const float4*)Xf + (size_t)gr * 32 + kc * 8 + asub * 4;
                    f0 = Xr[0]; f1 = Xr[1]; f2 = Xr[2]; f3 = Xr[3];
                } else {
                    f0 = f1 = f2 = f3 = make_float4(0.f, 0.f, 0.f, 0.f);
                }
                __half2 h0 = __floats2half2_rn(f0.x, f0.y), h1 = __floats2half2_rn(f0.z, f0.w);
                __half2 h2 = __floats2half2_rn(f1.x, f1.y), h3 = __floats2half2_rn(f1.z, f1.w);
                __half2 h4 = __floats2half2_rn(f2.x, f2.y), h5 = __floats2half2_rn(f2.z, f2.w);
                __half2 h6 = __floats2half2_rn(f3.x, f3.y), h7 = __floats2half2_rn(f3.z, f3.w);
                u0 = make_uint4(*(unsigned*)&h0, *(unsigned*)&h1, *(unsigned*)&h2, *(unsigned*)&h3);
                u1 = make_uint4(*(unsigned*)&h4, *(unsigned*)&h5, *(unsigned*)&h6, *(unsigned*)&h7);
            } else {
                if (gr < NN) {
                    const uint4* Ar = (const uint4*)(Ah + (size_t)gr * 128 + k0 + asub * 16);
                    u0 = Ar[0]; u1 = Ar[1];
                } else {
                    u0 = make_uint4(0u, 0u, 0u, 0u);
                    u1 = make_uint4(0u, 0u, 0u, 0u);
                }
            }
            uint4* dst = (uint4*)&sA[arow * SPITCH + asub * 16];
            dst[0] = u0; dst[1] = u1;
        }
        // ---- load B tile: BN rows x 32 halves (from pre-transposed fp16 weights)
        if (BN == 128 || t < 128) {
            int n = arow;            // for BN=64 only t<128 -> n<64
            const uint4* Br = (const uint4*)(Bt + (size_t)n * 128 + k0 + asub * 16);
            uint4* dst = (uint4*)&sB[n * SPITCH + asub * 16];
            dst[0] = Br[0]; dst[1] = Br[1];
        }
        __syncthreads();

        // ---- compute: 2 k16 steps
        #pragma unroll
        for (int ks = 0; ks < 2; ++ks) {
            unsigned af[MF][4];
            #pragma unroll
            for (int mf = 0; mf < MF; ++mf) {
                int r = m_w + mf * 16 + (lane & 15);
                int c = ks * 16 + ((lane >> 4) << 3);
                ldsm_x4(af[mf][0], af[mf][1], af[mf][2], af[mf][3],
                        smem_u32(&sA[r * SPITCH + c]));
            }
            unsigned bf[NF][2];
            #pragma unroll
            for (int nf = 0; nf < NF; ++nf) {
                int r = n_w + nf * 8 + (lane & 7);
                int c = ks * 16 + ((lane >> 3) & 1) * 8;
                ldsm_x2(bf[nf][0], bf[nf][1], smem_u32(&sB[r * SPITCH + c]));
            }
            #pragma unroll
            for (int mf = 0; mf < MF; ++mf)
                #pragma unroll
                for (int nf = 0; nf < NF; ++nf)
                    mma16816(acc[mf][nf][0], acc[mf][nf][1], acc[mf][nf][2], acc[mf][nf][3],
                             af[mf][0], af[mf][1], af[mf][2], af[mf][3],
                             bf[nf][0], bf[nf][1]);
        }
        __syncthreads();
    }

    // ---- epilogue: scale row m by dinv[m], store fp16
    #pragma unroll
    for (int mf = 0; mf < MF; ++mf) {
        int m0 = rowB + m_w + mf * 16 + (lane >> 2);
        float d0 = (m0     < NN) ? g_dinv[m0]     : 0.f;
        float d1 = (m0 + 8 < NN) ? g_dinv[m0 + 8] : 0.f;
        #pragma unroll
        for (int nf = 0; nf < NF; ++nf) {
            int n = n_w + nf * 8 + (lane & 3) * 2;
            if (m0 < NN) {
                __half2 p = __floats2half2_rn(acc[mf][nf][0] * d0, acc[mf][nf][1] * d0);
                *(__half2*)(Ch + (size_t)m0 * BN + n) = p;
            }
            if (m0 + 8 < NN) {
                __half2 p = __floats2half2_rn(acc[mf][nf][2] * d1, acc[mf][nf][3] * d1);
                *(__half2*)(Ch + (size_t)(m0 + 8) * BN + n) = p;
            }
        }
    }
}

// ---------------- gather SpMM (layer 1): 128 cols fp16, one warp per node ------
// g_h rows are pre-scaled by dinv[src]; result = relu(dinv[d]*(sum + self) + b1).
__global__ void spmm1(const float* __restrict__ b1) {
    int gw   = (blockIdx.x * blockDim.x + threadIdx.x) >> 5;
    int lane = threadIdx.x & 31;
    if (gw >= NN) return;
    const __half* __restrict__ H = g_h;
    float dv = g_dinv[gw];

    uint2 h0 = *(const uint2*)(H + (size_t)gw * 128 + lane * 4);
    float2 p0 = __half22float2(*(__half2*)&h0.x);
    float2 p1 = __half22float2(*(__half2*)&h0.y);
    float a0 = p0.x, a1 = p0.y, a2 = p1.x, a3 = p1.y;

    int e = g_off[gw], e1 = g_off[gw + 1];
    for (; e + 4 <= e1; e += 4) {
        int s0 = g_csr[e];
        int s1 = g_csr[e + 1];
        int s2 = g_csr[e + 2];
        int s3 = g_csr[e + 3];
        uint2 u0 = *(const uint2*)(H + (size_t)s0 * 128 + lane * 4);
        uint2 u1 = *(const uint2*)(H + (size_t)s1 * 128 + lane * 4);
        uint2 u2 = *(const uint2*)(H + (size_t)s2 * 128 + lane * 4);
        uint2 u3 = *(const uint2*)(H + (size_t)s3 * 128 + lane * 4);
        float2 q0 = __half22float2(*(__half2*)&u0.x), q1 = __half22float2(*(__half2*)&u0.y);
        float2 r0 = __half22float2(*(__half2*)&u1.x), r1 = __half22float2(*(__half2*)&u1.y);
        float2 w0 = __half22float2(*(__half2*)&u2.x), w1 = __half22float2(*(__half2*)&u2.y);
        float2 z0 = __half22float2(*(__half2*)&u3.x), z1 = __half22float2(*(__half2*)&u3.y);
        a0 += (q0.x + r0.x) + (w0.x + z0.x);
        a1 += (q0.y + r0.y) + (w0.y + z0.y);
        a2 += (q1.x + r1.x) + (w1.x + z1.x);
        a3 += (q1.y + r1.y) + (w1.y + z1.y);
    }
    for (; e < e1; ++e) {
        int s = g_csr[e];
        uint2 u = *(const uint2*)(H + (size_t)s * 128 + lane * 4);
        float2 q0 = __half22float2(*(__half2*)&u.x);
        float2 q1 = __half22float2(*(__half2*)&u.y);
        a0 += q0.x; a1 += q0.y; a2 += q1.x; a3 += q1.y;
    }
    float4 b = ((const float4*)b1)[lane];
    a0 = fmaxf(a0 * dv + b.x, 0.f);
    a1 = fmaxf(a1 * dv + b.y, 0.f);
    a2 = fmaxf(a2 * dv + b.z, 0.f);
    a3 = fmaxf(a3 * dv + b.w, 0.f);
    uint2 o;
    *(__half2*)&o.x = __floats2half2_rn(a0, a1);
    *(__half2*)&o.y = __floats2half2_rn(a2, a3);
    *(uint2*)(g_a + (size_t)gw * 128 + lane * 4) = o;
}

// ---------------- gather SpMM (layer 2): 64 cols fp16 in, fp32 out -------------
// g_t2 rows pre-scaled by dinv[src]; out = dinv[d]*(sum + self) + b2.
__global__ void spmm2(const float* __restrict__ b2, float* __restrict__ O) {
    int gw   = (blockIdx.x * blockDim.x + threadIdx.x) >> 5;
    int lane = threadIdx.x & 31;
    if (gw >= NN) return;
    const __half* __restrict__ T = g_t2;
    float dv = g_dinv[gw];

    float2 t0 = __half22float2(*(const __half2*)(T + (size_t)gw * 64 + lane * 2));
    float a0 = t0.x, a1 = t0.y;

    int e = g_off[gw], e1 = g_off[gw + 1];
    for (; e + 4 <= e1; e += 4) {
        int s0 = g_csr[e];
        int s1 = g_csr[e + 1];
        int s2 = g_csr[e + 2];
        int s3 = g_csr[e + 3];
        float2 v0 = __half22float2(*(const __half2*)(T + (size_t)s0 * 64 + lane * 2));
        float2 v1 = __half22float2(*(const __half2*)(T + (size_t)s1 * 64 + lane * 2));
        float2 v2 = __half22float2(*(const __half2*)(T + (size_t)s2 * 64 + lane * 2));
        float2 v3 = __half22float2(*(const __half2*)(T + (size_t)s3 * 64 + lane * 2));
        a0 += (v0.x + v1.x) + (v2.x + v3.x);
        a1 += (v0.y + v1.y) + (v2.y + v3.y);
    }
    for (; e < e1; ++e) {
        int s = g_csr[e];
        float2 v = __half22float2(*(const __half2*)(T + (size_t)s * 64 + lane * 2));
        a0 += v.x;
        a1 += v.y;
    }
    float2 b = ((const float2*)b2)[lane];
    ((float2*)O)[(size_t)gw * 32 + lane] = make_float2(a0 * dv + b.x, a1 * dv + b.y);
}

// ---------------- launch: fork CSR build onto a side stream ----------------------
extern "C" void kernel_launch(void* const* d_in, const int* in_sizes, int n_in,
                              void* d_out, int out_size) {
    const float* x  = (const float*)d_in[0];
    const int*   ei = (const int*)d_in[1];     // int32 [2, E]
    const float* W1 = (const float*)d_in[2];
    const float* b1 = (const float*)d_in[3];
    const float* W2 = (const float*)d_in[4];
    const float* b2 = (const float*)d_in[5];
    float*       out = (float*)d_out;

    // Fresh stream + events each call (kernel_launch runs only a handful of
    // times — correctness + capture — so not destroying them is harmless and
    // keeps everything capture-legal).
    cudaStream_t s1;
    cudaStreamCreateWithFlags(&s1, cudaStreamNonBlocking);
    cudaEvent_t evFork, evDinv, evFill;
    cudaEventCreateWithFlags(&evFork, cudaEventDisableTiming);
    cudaEventCreateWithFlags(&evDinv, cudaEventDisableTiming);
    cudaEventCreateWithFlags(&evFill, cudaEventDisableTiming);

    const int TB = 256;

    // fork: s1 branches off the (captured) main stream
    cudaEventRecord(evFork, 0);
    cudaStreamWaitEvent(s1, evFork, 0);

    // ---- CSR build chain on s1 (independent of GEMM1)
    k_zero_cnt <<<(NN + TB - 1) / TB, TB, 0, s1>>>();
    k_count    <<<(EE + TB - 1) / TB, TB, 0, s1>>>(ei);
    k_scan_part<<<SCAN_BLOCKS, SCAN_CHUNK, 0, s1>>>();
    cudaEventRecord(evDinv, s1);                 // dinv ready here
    k_scan_base<<<1, 128, 0, s1>>>();
    k_scan_add <<<SCAN_BLOCKS, SCAN_CHUNK, 0, s1>>>();
    k_fill     <<<(EE + TB - 1) / TB, TB, 0, s1>>>(ei);
    cudaEventRecord(evFill, s1);                 // CSR ready here

    // ---- main stream: weight prep runs concurrently with CSR build
    k_wprep<<<64, 256>>>(W1, W2);

    const int GB = (NN + 127) / 128;   // 782
    // hgemm1 epilogue needs dinv only
    cudaStreamWaitEvent(0, evDinv, 0);
    hgemm<128, 64, 32, 0><<<GB, 256>>>(x);

    // spmm1 needs the full CSR (join)
    cudaStreamWaitEvent(0, evFill, 0);
    spmm1<<<(NN * 32 + TB - 1) / TB, TB>>>(b1);

    hgemm<64, 32, 32, 1><<<GB, 256>>>(x /*unused*/);
    spmm2<<<(NN * 32 + TB - 1) / TB, TB>>>(b2, out);
}